// round 15
// baseline (speedup 1.0000x reference)
#include <cuda_runtime.h>
#include <cuda_bf16.h>

#define NN 50000
#define EE 800000
#define CAP 64   // bucket capacity per dst node (max in-degree ~40 here)

// ---------------------------------------------------------------------------
// Scratch (device globals — no allocation allowed)
// ---------------------------------------------------------------------------
__device__ float g_f[NN * 64];        // transformed features of current layer
__device__ float g_x[NN * 64];        // layer output / next-layer input
__device__ float g_el[NN * 4];        // attention left logits
__device__ float g_er[NN * 4];        // attention right logits

__device__ int g_cnt[NN];             // in-degree (atomic cursor during build)
__device__ int g_bucket[NN * CAP];    // per-dst list of (src*64)

__device__ __forceinline__ float lrelu(float x) {
    return x >= 0.f ? x : 0.2f * x;
}

// Packed dual-FMA: d = a*b + c elementwise on f32x2 (FFMA2, PTX-only)
__device__ __forceinline__ unsigned long long ffma2(unsigned long long a,
                                                    unsigned long long b,
                                                    unsigned long long c) {
    unsigned long long d;
    asm("fma.rn.f32x2 %0, %1, %2, %3;" : "=l"(d) : "l"(a), "l"(b), "l"(c));
    return d;
}

// ---------------------------------------------------------------------------
// Bucket build
// ---------------------------------------------------------------------------
__global__ void zero_cnt_kernel() {
    int i = blockIdx.x * blockDim.x + threadIdx.x;
    if (i < NN) g_cnt[i] = 0;
}

__global__ void scatter_kernel(const int* __restrict__ src,
                               const int* __restrict__ dst) {
    int e = blockIdx.x * blockDim.x + threadIdx.x;
    if (e >= EE) return;
    int d = dst[e];
    int p = atomicAdd(&g_cnt[d], 1);
    if (p < CAP) g_bucket[d * CAP + p] = src[e] << 6;   // prescaled src*64
}

// ---------------------------------------------------------------------------
// Fused GEMM + attention-logit kernel, 4x4 blocking with FFMA2 mainloop.
// Column pairs packed for free from row-major Ws (LDS.128 -> ulonglong2);
// x duplicated in smem ({v,v} per element) so no ALU packing is needed.
// Per k0-quad: 12 LDS.128 + 32 FFMA2 (64 MACs) -> FMA-pipe cost halved.
// ---------------------------------------------------------------------------
template <int K, int H>
__global__ void __launch_bounds__(256) gemm_elr_kernel(
        const float* __restrict__ x, const float* __restrict__ W,
        const float* __restrict__ al, const float* __restrict__ ar) {
    constexpr int NODES = 64;
    __shared__ __align__(16) float  Ws[K * 64];
    __shared__ __align__(16) float2 xs2[NODES * K];   // duplicated x
    __shared__ float s_pl[NODES][4];
    __shared__ float s_pr[NODES][4];

    const float* xp = x ? x : g_x;
    int tid = threadIdx.x;
    int n0  = blockIdx.x * NODES;

    {
        const float4* Wv = (const float4*)W;
        float4* Wsv = (float4*)Ws;
        for (int i = tid; i < K * 16; i += 256) Wsv[i] = Wv[i];
        for (int i = tid; i < NODES * K / 4; i += 256) {
            int node = n0 + (i * 4) / K;
            float4 v = make_float4(0.f, 0.f, 0.f, 0.f);
            if (node < NN) v = *(const float4*)&xp[n0 * K + i * 4];
            // duplicated store: element e -> {v,v}
            *(float4*)&xs2[i * 4]     = make_float4(v.x, v.x, v.y, v.y);
            *(float4*)&xs2[i * 4 + 2] = make_float4(v.z, v.z, v.w, v.w);
        }
    }
    __syncthreads();

    int cg = tid & 15;        // column group: cols cg*4 .. cg*4+3
    int rg = tid >> 4;        // row group: rows rg*4 .. rg*4+3
    int j4 = cg * 4;

    unsigned long long accA[4], accB[4];   // col pair (j4,j4+1) / (j4+2,j4+3)
#pragma unroll
    for (int r = 0; r < 4; ++r) { accA[r] = 0ull; accB[r] = 0ull; }

    for (int k0 = 0; k0 < K; k0 += 4) {
        ulonglong2 w0 = *(const ulonglong2*)&Ws[(k0 + 0) * 64 + j4];
        ulonglong2 w1 = *(const ulonglong2*)&Ws[(k0 + 1) * 64 + j4];
        ulonglong2 w2 = *(const ulonglong2*)&Ws[(k0 + 2) * 64 + j4];
        ulonglong2 w3 = *(const ulonglong2*)&Ws[(k0 + 3) * 64 + j4];
#pragma unroll
        for (int r = 0; r < 4; ++r) {
            const float2* xr = &xs2[(rg * 4 + r) * K + k0];
            ulonglong2 xd01 = *(const ulonglong2*)xr;        // {x0,x0},{x1,x1}
            ulonglong2 xd23 = *(const ulonglong2*)(xr + 2);  // {x2,x2},{x3,x3}
            accA[r] = ffma2(xd01.x, w0.x, accA[r]);
            accB[r] = ffma2(xd01.x, w0.y, accB[r]);
            accA[r] = ffma2(xd01.y, w1.x, accA[r]);
            accB[r] = ffma2(xd01.y, w1.y, accB[r]);
            accA[r] = ffma2(xd23.x, w2.x, accA[r]);
            accB[r] = ffma2(xd23.x, w2.y, accB[r]);
            accA[r] = ffma2(xd23.y, w3.x, accA[r]);
            accB[r] = ffma2(xd23.y, w3.y, accB[r]);
        }
    }

    float4 al4 = *(const float4*)&al[j4];
    float4 ar4 = *(const float4*)&ar[j4];

#pragma unroll
    for (int r = 0; r < 4; ++r) {
        float4 acc;
        acc.x = __uint_as_float((unsigned)(accA[r] & 0xffffffffu));
        acc.y = __uint_as_float((unsigned)(accA[r] >> 32));
        acc.z = __uint_as_float((unsigned)(accB[r] & 0xffffffffu));
        acc.w = __uint_as_float((unsigned)(accB[r] >> 32));

        int nloc = rg * 4 + r;
        int n = n0 + nloc;
        if (n < NN) *(float4*)&g_f[n * 64 + j4] = acc;

        float pl = acc.x * al4.x + acc.y * al4.y +
                   acc.z * al4.z + acc.w * al4.w;
        float pr = acc.x * ar4.x + acc.y * ar4.y +
                   acc.z * ar4.z + acc.w * ar4.w;
        pl += __shfl_xor_sync(0xffffffffu, pl, 1);
        pr += __shfl_xor_sync(0xffffffffu, pr, 1);
        pl += __shfl_xor_sync(0xffffffffu, pl, 2);
        pr += __shfl_xor_sync(0xffffffffu, pr, 2);
        if ((cg & 3) == 0) {
            s_pl[nloc][cg >> 2] = pl;
            s_pr[nloc][cg >> 2] = pr;
        }
    }
    __syncthreads();

    if (H == 4) {
        int nloc = tid >> 2, h = tid & 3;
        int n = n0 + nloc;
        if (n < NN) {
            g_el[n * 4 + h] = s_pl[nloc][h];
            g_er[n * 4 + h] = s_pr[nloc][h];
        }
    } else {
        if (tid < NODES) {
            int n = n0 + tid;
            if (n < NN) {
                g_el[n] = s_pl[tid][0] + s_pl[tid][1] + s_pl[tid][2] + s_pl[tid][3];
                g_er[n] = s_pr[tid][0] + s_pr[tid][1] + s_pr[tid][2] + s_pr[tid][3];
            }
        }
    }
}

// ---------------------------------------------------------------------------
// Fused single-pass softmax + aggregation + bias + ELU (R14, proven).
// TWO nodes per warp (half-warp per node; lane owns 4 channels). Single
// up-front load phase (MLP=4), one syncwarp, one unbroken aggregation loop.
// ---------------------------------------------------------------------------
template <int H>
__global__ void __launch_bounds__(256) gat_edge_kernel(const float* __restrict__ b,
                                                       float* __restrict__ out,
                                                       int do_elu) {
    __shared__ int s_off[8][2][CAP];                        // src*64
    __shared__ __align__(16) float s_ex[8][2][CAP * H];

    int wid  = threadIdx.x >> 5;
    int lane = threadIdx.x & 31;
    int half = lane >> 4;
    int li   = lane & 15;
    int n = blockIdx.x * 16 + wid * 2 + half;
    bool valid = (n < NN);
    int cnt = 0;
    const int* bucket = nullptr;
    if (valid) {
        cnt = g_cnt[n];
        if (cnt > CAP) cnt = CAP;
        bucket = &g_bucket[n * CAP];
    }

    float er_h[H];
    if (valid) {
        if (H == 4) {
            float4 e4 = *(const float4*)&g_er[n * 4];
            er_h[0] = e4.x; er_h[1] = e4.y; er_h[2] = e4.z; er_h[3] = e4.w;
        } else {
            er_h[0] = g_er[n];
        }
    }

    float ssum[H];
#pragma unroll
    for (int h = 0; h < H; ++h) ssum[h] = 0.f;

    // ---- load phase: entire degree, all loads issued with max MLP ----
    int offr[4];
#pragma unroll
    for (int c = 0; c < 4; ++c) {
        int idx = li + c * 16;
        offr[c] = (idx < cnt) ? bucket[idx] : -1;
    }
#pragma unroll
    for (int c = 0; c < 4; ++c) {
        int idx = li + c * 16;
        if (offr[c] >= 0) {
            int off = offr[c];
            s_off[wid][half][idx] = off;
            if (H == 4) {
                float4 e4 = *(const float4*)&g_el[off >> 4];   // g_el[src*4]
                float v0 = __expf(lrelu(e4.x + er_h[0]));
                float v1 = __expf(lrelu(e4.y + er_h[1]));
                float v2 = __expf(lrelu(e4.z + er_h[2]));
                float v3 = __expf(lrelu(e4.w + er_h[3]));
                ssum[0] += v0; ssum[1] += v1; ssum[2] += v2; ssum[3] += v3;
                *(float4*)&s_ex[wid][half][idx * 4] = make_float4(v0, v1, v2, v3);
            } else {
                float v0 = __expf(lrelu(g_el[off >> 6] + er_h[0]));
                ssum[0] += v0;
                s_ex[wid][half][idx] = v0;
            }
        }
    }
    __syncwarp();

    // ---- aggregation: one unbroken loop over all edges of own node ----
    float4 acc = make_float4(0.f, 0.f, 0.f, 0.f);
    int hh = (H == 4) ? (li >> 2) : 0;
#pragma unroll 4
    for (int j = 0; j < cnt; ++j) {
        int off = s_off[wid][half][j];
        float c = (H == 4) ? s_ex[wid][half][j * 4 + hh]
                           : s_ex[wid][half][j];
        float4 fv = *(const float4*)&g_f[off + li * 4];
        acc.x = fmaf(c, fv.x, acc.x);
        acc.y = fmaf(c, fv.y, acc.y);
        acc.z = fmaf(c, fv.z, acc.z);
        acc.w = fmaf(c, fv.w, acc.w);
    }

    // softmax denominators: reduce within the half-warp
#pragma unroll
    for (int o = 8; o > 0; o >>= 1)
#pragma unroll
        for (int h = 0; h < H; ++h)
            ssum[h] += __shfl_xor_sync(0xffffffffu, ssum[h], o);

    if (valid) {
        float4 bv = *(const float4*)&b[li * 4];
        float4 v;
        if (cnt > 0) {
            float inv = 1.f / ssum[hh];
            v.x = acc.x * inv + bv.x;
            v.y = acc.y * inv + bv.y;
            v.z = acc.z * inv + bv.z;
            v.w = acc.w * inv + bv.w;
        } else {
            v = bv;
        }
        if (do_elu) {
            v.x = v.x > 0.f ? v.x : expm1f(v.x);
            v.y = v.y > 0.f ? v.y : expm1f(v.y);
            v.z = v.z > 0.f ? v.z : expm1f(v.z);
            v.w = v.w > 0.f ? v.w : expm1f(v.w);
        }
        float* op = out ? out : g_x;
        *(float4*)&op[n * 64 + li * 4] = v;
    }
}

// ---------------------------------------------------------------------------
// Host driver — bucket build overlapped with layer-0 GEMM on a side stream.
// ---------------------------------------------------------------------------
extern "C" void kernel_launch(void* const* d_in, const int* in_sizes, int n_in,
                              void* d_out, int out_size) {
    const float* h   = (const float*)d_in[0];
    const int*   src = (const int*)  d_in[1];
    const int*   dst = (const int*)  d_in[2];
    const float* W0  = (const float*)d_in[3];
    const float* al0 = (const float*)d_in[4];
    const float* ar0 = (const float*)d_in[5];
    const float* b0  = (const float*)d_in[6];
    const float* W1  = (const float*)d_in[7];
    const float* al1 = (const float*)d_in[8];
    const float* ar1 = (const float*)d_in[9];
    const float* b1  = (const float*)d_in[10];
    const float* W2  = (const float*)d_in[11];
    const float* al2 = (const float*)d_in[12];
    const float* ar2 = (const float*)d_in[13];
    const float* b2  = (const float*)d_in[14];

    static cudaStream_t s2 = nullptr;
    static cudaEvent_t evFork = nullptr, evJoin = nullptr;
    if (!s2) {
        cudaStreamCreateWithFlags(&s2, cudaStreamNonBlocking);
        cudaEventCreateWithFlags(&evFork, cudaEventDisableTiming);
        cudaEventCreateWithFlags(&evJoin, cudaEventDisableTiming);
    }

    // Fork: bucket build on s2, layer-0 GEMM on main stream.
    cudaEventRecord(evFork, 0);
    cudaStreamWaitEvent(s2, evFork, 0);

    zero_cnt_kernel<<<(NN + 255) / 256, 256, 0, s2>>>();
    scatter_kernel <<<(EE + 255) / 256, 256, 0, s2>>>(src, dst);
    cudaEventRecord(evJoin, s2);

    int gblocks = (NN + 63) / 64;   // 782

    gemm_elr_kernel<128, 4><<<gblocks, 256>>>(h, W0, al0, ar0);

    cudaStreamWaitEvent(0, evJoin, 0);

    int eblocks = (NN + 15) / 16;   // 3125

    gat_edge_kernel<4><<<eblocks, 256>>>(b0, nullptr, 1);

    gemm_elr_kernel<64, 4><<<gblocks, 256>>>(nullptr, W1, al1, ar1);
    gat_edge_kernel<4><<<eblocks, 256>>>(b1, nullptr, 1);

    gemm_elr_kernel<64, 1><<<gblocks, 256>>>(nullptr, W2, al2, ar2);
    gat_edge_kernel<1><<<eblocks, 256>>>(b2, (float*)d_out, 0);
}

// round 16
// speedup vs baseline: 1.0408x; 1.0408x over previous
#include <cuda_runtime.h>
#include <cuda_bf16.h>

#define NN 50000
#define EE 800000
#define CAP 48   // bucket capacity; mean deg 16, P(deg>48) ~ 1e-10 per node

// ---------------------------------------------------------------------------
// Scratch (device globals — no allocation allowed)
// ---------------------------------------------------------------------------
__device__ float g_f[NN * 64];        // transformed features of current layer
__device__ float g_x[NN * 64];        // layer output / next-layer input
__device__ float g_el[NN * 4];        // attention left logits
__device__ float g_er[NN * 4];        // attention right logits

__device__ int g_cnt[NN];             // in-degree (atomic cursor during build)
__device__ int g_bucket[NN * CAP];    // per-dst list of (src*64)

__device__ __forceinline__ float lrelu(float x) {
    return x >= 0.f ? x : 0.2f * x;
}

// ---------------------------------------------------------------------------
// Bucket build
// ---------------------------------------------------------------------------
__global__ void zero_cnt_kernel() {
    int i = blockIdx.x * blockDim.x + threadIdx.x;
    if (i < NN) g_cnt[i] = 0;
}

__global__ void scatter_kernel(const int* __restrict__ src,
                               const int* __restrict__ dst) {
    int e = blockIdx.x * blockDim.x + threadIdx.x;
    if (e >= EE) return;
    int d = dst[e];
    int p = atomicAdd(&g_cnt[d], 1);
    if (p < CAP) g_bucket[d * CAP + p] = src[e] << 6;   // prescaled src*64
}

// ---------------------------------------------------------------------------
// Fused GEMM + attention-logit kernel, 4x4 register blocking (R13, proven).
// ---------------------------------------------------------------------------
template <int K, int H>
__global__ void __launch_bounds__(256) gemm_elr_kernel(
        const float* __restrict__ x, const float* __restrict__ W,
        const float* __restrict__ al, const float* __restrict__ ar) {
    constexpr int NODES = 64;
    __shared__ __align__(16) float Ws[K * 64];
    __shared__ __align__(16) float xs[NODES * K];
    __shared__ float s_pl[NODES][4];
    __shared__ float s_pr[NODES][4];

    const float* xp = x ? x : g_x;
    int tid = threadIdx.x;
    int n0  = blockIdx.x * NODES;

    {
        const float4* Wv = (const float4*)W;
        float4* Wsv = (float4*)Ws;
        for (int i = tid; i < K * 16; i += 256) Wsv[i] = Wv[i];
        float4* xsv = (float4*)xs;
        for (int i = tid; i < NODES * K / 4; i += 256) {
            int node = n0 + (i * 4) / K;
            float4 v = make_float4(0.f, 0.f, 0.f, 0.f);
            if (node < NN) v = *(const float4*)&xp[n0 * K + i * 4];
            xsv[i] = v;
        }
    }
    __syncthreads();

    int cg = tid & 15;        // column group: cols cg*4 .. cg*4+3
    int rg = tid >> 4;        // row group: rows rg*4 .. rg*4+3
    int j4 = cg * 4;

    float4 acc[4];
#pragma unroll
    for (int r = 0; r < 4; ++r) acc[r] = make_float4(0.f, 0.f, 0.f, 0.f);

    for (int k0 = 0; k0 < K; k0 += 4) {
        float4 w0 = *(const float4*)&Ws[(k0 + 0) * 64 + j4];
        float4 w1 = *(const float4*)&Ws[(k0 + 1) * 64 + j4];
        float4 w2 = *(const float4*)&Ws[(k0 + 2) * 64 + j4];
        float4 w3 = *(const float4*)&Ws[(k0 + 3) * 64 + j4];
#pragma unroll
        for (int r = 0; r < 4; ++r) {
            float4 xv = *(const float4*)&xs[(rg * 4 + r) * K + k0];
            acc[r].x = fmaf(xv.x, w0.x, acc[r].x);
            acc[r].y = fmaf(xv.x, w0.y, acc[r].y);
            acc[r].z = fmaf(xv.x, w0.z, acc[r].z);
            acc[r].w = fmaf(xv.x, w0.w, acc[r].w);
            acc[r].x = fmaf(xv.y, w1.x, acc[r].x);
            acc[r].y = fmaf(xv.y, w1.y, acc[r].y);
            acc[r].z = fmaf(xv.y, w1.z, acc[r].z);
            acc[r].w = fmaf(xv.y, w1.w, acc[r].w);
            acc[r].x = fmaf(xv.z, w2.x, acc[r].x);
            acc[r].y = fmaf(xv.z, w2.y, acc[r].y);
            acc[r].z = fmaf(xv.z, w2.z, acc[r].z);
            acc[r].w = fmaf(xv.z, w2.w, acc[r].w);
            acc[r].x = fmaf(xv.w, w3.x, acc[r].x);
            acc[r].y = fmaf(xv.w, w3.y, acc[r].y);
            acc[r].z = fmaf(xv.w, w3.z, acc[r].z);
            acc[r].w = fmaf(xv.w, w3.w, acc[r].w);
        }
    }

    float4 al4 = *(const float4*)&al[j4];
    float4 ar4 = *(const float4*)&ar[j4];

#pragma unroll
    for (int r = 0; r < 4; ++r) {
        int nloc = rg * 4 + r;
        int n = n0 + nloc;
        if (n < NN) *(float4*)&g_f[n * 64 + j4] = acc[r];

        float pl = acc[r].x * al4.x + acc[r].y * al4.y +
                   acc[r].z * al4.z + acc[r].w * al4.w;
        float pr = acc[r].x * ar4.x + acc[r].y * ar4.y +
                   acc[r].z * ar4.z + acc[r].w * ar4.w;
        pl += __shfl_xor_sync(0xffffffffu, pl, 1);
        pr += __shfl_xor_sync(0xffffffffu, pr, 1);
        pl += __shfl_xor_sync(0xffffffffu, pl, 2);
        pr += __shfl_xor_sync(0xffffffffu, pr, 2);
        if ((cg & 3) == 0) {
            s_pl[nloc][cg >> 2] = pl;
            s_pr[nloc][cg >> 2] = pr;
        }
    }
    __syncthreads();

    if (H == 4) {
        int nloc = tid >> 2, h = tid & 3;
        int n = n0 + nloc;
        if (n < NN) {
            g_el[n * 4 + h] = s_pl[nloc][h];
            g_er[n * 4 + h] = s_pr[nloc][h];
        }
    } else {
        if (tid < NODES) {
            int n = n0 + tid;
            if (n < NN) {
                g_el[n] = s_pl[tid][0] + s_pl[tid][1] + s_pl[tid][2] + s_pl[tid][3];
                g_er[n] = s_pr[tid][0] + s_pr[tid][1] + s_pr[tid][2] + s_pr[tid][3];
            }
        }
    }
}

// ---------------------------------------------------------------------------
// Fused single-pass softmax + aggregation + bias + ELU.
// TWO nodes per HALF-WARP (mean degree is only 16 — one ~700cy load chain
// now covers ~32 edges of work). Interleaved load phase for both nodes
// (bucket MLP 6, then all el gathers independent), then two unbroken agg
// loops; node A is written out before node B's accumulator lives.
// ---------------------------------------------------------------------------
template <int H>
__global__ void __launch_bounds__(256) gat_edge_kernel(const float* __restrict__ b,
                                                       float* __restrict__ out,
                                                       int do_elu) {
    __shared__ int s_off[16][2][CAP];                       // src*64
    __shared__ __align__(16) float s_ex[16][2][CAP * H];

    int wid  = threadIdx.x >> 5;
    int lane = threadIdx.x & 31;
    int half = lane >> 4;
    int li   = lane & 15;
    int hw   = wid * 2 + half;                              // 0..15
    int na = blockIdx.x * 32 + hw * 2;
    int nb = na + 1;
    bool va = (na < NN), vb = (nb < NN);

    int cntA = 0, cntB = 0;
    if (va) { cntA = g_cnt[na]; if (cntA > CAP) cntA = CAP; }
    if (vb) { cntB = g_cnt[nb]; if (cntB > CAP) cntB = CAP; }
    const int* bukA = &g_bucket[na * CAP];
    const int* bukB = &g_bucket[nb * CAP];

    float erA[H], erB[H];
    if (va) {
        if (H == 4) {
            float4 e4 = *(const float4*)&g_er[na * 4];
            erA[0] = e4.x; erA[1] = e4.y; erA[2] = e4.z; erA[3] = e4.w;
        } else erA[0] = g_er[na];
    }
    if (vb) {
        if (H == 4) {
            float4 e4 = *(const float4*)&g_er[nb * 4];
            erB[0] = e4.x; erB[1] = e4.y; erB[2] = e4.z; erB[3] = e4.w;
        } else erB[0] = g_er[nb];
    }

    float ssA[H], ssB[H];
#pragma unroll
    for (int h = 0; h < H; ++h) { ssA[h] = 0.f; ssB[h] = 0.f; }

    // ---- load phase: both nodes' buckets issued together (MLP 6) ----
    int offA[3], offB[3];
#pragma unroll
    for (int c = 0; c < 3; ++c) {
        int idx = li + c * 16;
        offA[c] = (idx < cntA) ? bukA[idx] : -1;
        offB[c] = (idx < cntB) ? bukB[idx] : -1;
    }
    // el gathers + exp for both nodes (all independent)
#pragma unroll
    for (int c = 0; c < 3; ++c) {
        int idx = li + c * 16;
        if (offA[c] >= 0) {
            int off = offA[c];
            s_off[hw][0][idx] = off;
            if (H == 4) {
                float4 e4 = *(const float4*)&g_el[off >> 4];
                float v0 = __expf(lrelu(e4.x + erA[0]));
                float v1 = __expf(lrelu(e4.y + erA[1]));
                float v2 = __expf(lrelu(e4.z + erA[2]));
                float v3 = __expf(lrelu(e4.w + erA[3]));
                ssA[0] += v0; ssA[1] += v1; ssA[2] += v2; ssA[3] += v3;
                *(float4*)&s_ex[hw][0][idx * 4] = make_float4(v0, v1, v2, v3);
            } else {
                float v0 = __expf(lrelu(g_el[off >> 6] + erA[0]));
                ssA[0] += v0;
                s_ex[hw][0][idx] = v0;
            }
        }
        if (offB[c] >= 0) {
            int off = offB[c];
            s_off[hw][1][idx] = off;
            if (H == 4) {
                float4 e4 = *(const float4*)&g_el[off >> 4];
                float v0 = __expf(lrelu(e4.x + erB[0]));
                float v1 = __expf(lrelu(e4.y + erB[1]));
                float v2 = __expf(lrelu(e4.z + erB[2]));
                float v3 = __expf(lrelu(e4.w + erB[3]));
                ssB[0] += v0; ssB[1] += v1; ssB[2] += v2; ssB[3] += v3;
                *(float4*)&s_ex[hw][1][idx * 4] = make_float4(v0, v1, v2, v3);
            } else {
                float v0 = __expf(lrelu(g_el[off >> 6] + erB[0]));
                ssB[0] += v0;
                s_ex[hw][1][idx] = v0;
            }
        }
    }
    __syncwarp();

    // softmax denominators: reduce within the half-warp (both nodes)
#pragma unroll
    for (int o = 8; o > 0; o >>= 1)
#pragma unroll
        for (int h = 0; h < H; ++h) {
            ssA[h] += __shfl_xor_sync(0xffffffffu, ssA[h], o);
            ssB[h] += __shfl_xor_sync(0xffffffffu, ssB[h], o);
        }

    int hh = (H == 4) ? (li >> 2) : 0;     // head of channels li*4..li*4+3
    float* op = out ? out : g_x;
    float4 bv = *(const float4*)&b[li * 4];

    // ---- node A: aggregate then write (frees accumulator before B) ----
    {
        float4 acc = make_float4(0.f, 0.f, 0.f, 0.f);
#pragma unroll 4
        for (int j = 0; j < cntA; ++j) {
            int off = s_off[hw][0][j];
            float c = (H == 4) ? s_ex[hw][0][j * 4 + hh] : s_ex[hw][0][j];
            float4 fv = *(const float4*)&g_f[off + li * 4];
            acc.x = fmaf(c, fv.x, acc.x);
            acc.y = fmaf(c, fv.y, acc.y);
            acc.z = fmaf(c, fv.z, acc.z);
            acc.w = fmaf(c, fv.w, acc.w);
        }
        if (va) {
            float4 v;
            if (cntA > 0) {
                float inv = 1.f / ssA[hh];
                v.x = acc.x * inv + bv.x;
                v.y = acc.y * inv + bv.y;
                v.z = acc.z * inv + bv.z;
                v.w = acc.w * inv + bv.w;
            } else v = bv;
            if (do_elu) {
                v.x = v.x > 0.f ? v.x : expm1f(v.x);
                v.y = v.y > 0.f ? v.y : expm1f(v.y);
                v.z = v.z > 0.f ? v.z : expm1f(v.z);
                v.w = v.w > 0.f ? v.w : expm1f(v.w);
            }
            *(float4*)&op[na * 64 + li * 4] = v;
        }
    }

    // ---- node B ----
    {
        float4 acc = make_float4(0.f, 0.f, 0.f, 0.f);
#pragma unroll 4
        for (int j = 0; j < cntB; ++j) {
            int off = s_off[hw][1][j];
            float c = (H == 4) ? s_ex[hw][1][j * 4 + hh] : s_ex[hw][1][j];
            float4 fv = *(const float4*)&g_f[off + li * 4];
            acc.x = fmaf(c, fv.x, acc.x);
            acc.y = fmaf(c, fv.y, acc.y);
            acc.z = fmaf(c, fv.z, acc.z);
            acc.w = fmaf(c, fv.w, acc.w);
        }
        if (vb) {
            float4 v;
            if (cntB > 0) {
                float inv = 1.f / ssB[hh];
                v.x = acc.x * inv + bv.x;
                v.y = acc.y * inv + bv.y;
                v.z = acc.z * inv + bv.z;
                v.w = acc.w * inv + bv.w;
            } else v = bv;
            if (do_elu) {
                v.x = v.x > 0.f ? v.x : expm1f(v.x);
                v.y = v.y > 0.f ? v.y : expm1f(v.y);
                v.z = v.z > 0.f ? v.z : expm1f(v.z);
                v.w = v.w > 0.f ? v.w : expm1f(v.w);
            }
            *(float4*)&op[nb * 64 + li * 4] = v;
        }
    }
}

// ---------------------------------------------------------------------------
// Host driver — bucket build overlapped with layer-0 GEMM on a side stream.
// ---------------------------------------------------------------------------
extern "C" void kernel_launch(void* const* d_in, const int* in_sizes, int n_in,
                              void* d_out, int out_size) {
    const float* h   = (const float*)d_in[0];
    const int*   src = (const int*)  d_in[1];
    const int*   dst = (const int*)  d_in[2];
    const float* W0  = (const float*)d_in[3];
    const float* al0 = (const float*)d_in[4];
    const float* ar0 = (const float*)d_in[5];
    const float* b0  = (const float*)d_in[6];
    const float* W1  = (const float*)d_in[7];
    const float* al1 = (const float*)d_in[8];
    const float* ar1 = (const float*)d_in[9];
    const float* b1  = (const float*)d_in[10];
    const float* W2  = (const float*)d_in[11];
    const float* al2 = (const float*)d_in[12];
    const float* ar2 = (const float*)d_in[13];
    const float* b2  = (const float*)d_in[14];

    static cudaStream_t s2 = nullptr;
    static cudaEvent_t evFork = nullptr, evJoin = nullptr;
    if (!s2) {
        cudaStreamCreateWithFlags(&s2, cudaStreamNonBlocking);
        cudaEventCreateWithFlags(&evFork, cudaEventDisableTiming);
        cudaEventCreateWithFlags(&evJoin, cudaEventDisableTiming);
    }

    // Fork: bucket build on s2, layer-0 GEMM on main stream.
    cudaEventRecord(evFork, 0);
    cudaStreamWaitEvent(s2, evFork, 0);

    zero_cnt_kernel<<<(NN + 255) / 256, 256, 0, s2>>>();
    scatter_kernel <<<(EE + 255) / 256, 256, 0, s2>>>(src, dst);
    cudaEventRecord(evJoin, s2);

    int gblocks = (NN + 63) / 64;   // 782

    gemm_elr_kernel<128, 4><<<gblocks, 256>>>(h, W0, al0, ar0);

    cudaStreamWaitEvent(0, evJoin, 0);

    int eblocks = (NN + 31) / 32;   // 1563

    gat_edge_kernel<4><<<eblocks, 256>>>(b0, nullptr, 1);

    gemm_elr_kernel<64, 4><<<gblocks, 256>>>(nullptr, W1, al1, ar1);
    gat_edge_kernel<4><<<eblocks, 256>>>(b1, nullptr, 1);

    gemm_elr_kernel<64, 1><<<gblocks, 256>>>(nullptr, W2, al2, ar2);
    gat_edge_kernel<1><<<eblocks, 256>>>(b2, (float*)d_out, 0);
}

// round 17
// speedup vs baseline: 1.0473x; 1.0062x over previous
#include <cuda_runtime.h>
#include <cuda_bf16.h>

#define NN 50000
#define EE 800000
#define CAP 64   // bucket capacity per dst node (max in-degree ~40 here)

// ---------------------------------------------------------------------------
// Scratch (device globals — no allocation allowed)
// ---------------------------------------------------------------------------
__device__ float g_f[NN * 64];        // transformed features of current layer
__device__ float g_x[NN * 64];        // layer output / next-layer input
__device__ float g_el[NN * 4];        // attention left logits
__device__ float g_er[NN * 4];        // attention right logits

__device__ int g_cnt[NN];             // in-degree (atomic cursor during build)
__device__ int g_bucket[NN * CAP];    // per-dst list of (src*64)

__device__ __forceinline__ float lrelu(float x) {
    return x >= 0.f ? x : 0.2f * x;
}

// ---------------------------------------------------------------------------
// Bucket build
// ---------------------------------------------------------------------------
__global__ void zero_cnt_kernel() {
    int i = blockIdx.x * blockDim.x + threadIdx.x;
    if (i < NN) g_cnt[i] = 0;
}

__global__ void scatter_kernel(const int* __restrict__ src,
                               const int* __restrict__ dst) {
    int e = blockIdx.x * blockDim.x + threadIdx.x;
    if (e >= EE) return;
    int d = dst[e];
    int p = atomicAdd(&g_cnt[d], 1);
    if (p < CAP) g_bucket[d * CAP + p] = src[e] << 6;   // prescaled src*64
}

// ---------------------------------------------------------------------------
// Fused GEMM + attention-logit kernel, 4x4 register blocking (R13, proven).
// ---------------------------------------------------------------------------
template <int K, int H>
__global__ void __launch_bounds__(256) gemm_elr_kernel(
        const float* __restrict__ x, const float* __restrict__ W,
        const float* __restrict__ al, const float* __restrict__ ar) {
    constexpr int NODES = 64;
    __shared__ __align__(16) float Ws[K * 64];
    __shared__ __align__(16) float xs[NODES * K];
    __shared__ float s_pl[NODES][4];
    __shared__ float s_pr[NODES][4];

    const float* xp = x ? x : g_x;
    int tid = threadIdx.x;
    int n0  = blockIdx.x * NODES;

    {
        const float4* Wv = (const float4*)W;
        float4* Wsv = (float4*)Ws;
        for (int i = tid; i < K * 16; i += 256) Wsv[i] = Wv[i];
        float4* xsv = (float4*)xs;
        for (int i = tid; i < NODES * K / 4; i += 256) {
            int node = n0 + (i * 4) / K;
            float4 v = make_float4(0.f, 0.f, 0.f, 0.f);
            if (node < NN) v = *(const float4*)&xp[n0 * K + i * 4];
            xsv[i] = v;
        }
    }
    __syncthreads();

    int cg = tid & 15;        // column group: cols cg*4 .. cg*4+3
    int rg = tid >> 4;        // row group: rows rg*4 .. rg*4+3
    int j4 = cg * 4;

    float4 acc[4];
#pragma unroll
    for (int r = 0; r < 4; ++r) acc[r] = make_float4(0.f, 0.f, 0.f, 0.f);

    for (int k0 = 0; k0 < K; k0 += 4) {
        float4 w0 = *(const float4*)&Ws[(k0 + 0) * 64 + j4];
        float4 w1 = *(const float4*)&Ws[(k0 + 1) * 64 + j4];
        float4 w2 = *(const float4*)&Ws[(k0 + 2) * 64 + j4];
        float4 w3 = *(const float4*)&Ws[(k0 + 3) * 64 + j4];
#pragma unroll
        for (int r = 0; r < 4; ++r) {
            float4 xv = *(const float4*)&xs[(rg * 4 + r) * K + k0];
            acc[r].x = fmaf(xv.x, w0.x, acc[r].x);
            acc[r].y = fmaf(xv.x, w0.y, acc[r].y);
            acc[r].z = fmaf(xv.x, w0.z, acc[r].z);
            acc[r].w = fmaf(xv.x, w0.w, acc[r].w);
            acc[r].x = fmaf(xv.y, w1.x, acc[r].x);
            acc[r].y = fmaf(xv.y, w1.y, acc[r].y);
            acc[r].z = fmaf(xv.y, w1.z, acc[r].z);
            acc[r].w = fmaf(xv.y, w1.w, acc[r].w);
            acc[r].x = fmaf(xv.z, w2.x, acc[r].x);
            acc[r].y = fmaf(xv.z, w2.y, acc[r].y);
            acc[r].z = fmaf(xv.z, w2.z, acc[r].z);
            acc[r].w = fmaf(xv.z, w2.w, acc[r].w);
            acc[r].x = fmaf(xv.w, w3.x, acc[r].x);
            acc[r].y = fmaf(xv.w, w3.y, acc[r].y);
            acc[r].z = fmaf(xv.w, w3.z, acc[r].z);
            acc[r].w = fmaf(xv.w, w3.w, acc[r].w);
        }
    }

    float4 al4 = *(const float4*)&al[j4];
    float4 ar4 = *(const float4*)&ar[j4];

#pragma unroll
    for (int r = 0; r < 4; ++r) {
        int nloc = rg * 4 + r;
        int n = n0 + nloc;
        if (n < NN) *(float4*)&g_f[n * 64 + j4] = acc[r];

        float pl = acc[r].x * al4.x + acc[r].y * al4.y +
                   acc[r].z * al4.z + acc[r].w * al4.w;
        float pr = acc[r].x * ar4.x + acc[r].y * ar4.y +
                   acc[r].z * ar4.z + acc[r].w * ar4.w;
        pl += __shfl_xor_sync(0xffffffffu, pl, 1);
        pr += __shfl_xor_sync(0xffffffffu, pr, 1);
        pl += __shfl_xor_sync(0xffffffffu, pl, 2);
        pr += __shfl_xor_sync(0xffffffffu, pr, 2);
        if ((cg & 3) == 0) {
            s_pl[nloc][cg >> 2] = pl;
            s_pr[nloc][cg >> 2] = pr;
        }
    }
    __syncthreads();

    if (H == 4) {
        int nloc = tid >> 2, h = tid & 3;
        int n = n0 + nloc;
        if (n < NN) {
            g_el[n * 4 + h] = s_pl[nloc][h];
            g_er[n * 4 + h] = s_pr[nloc][h];
        }
    } else {
        if (tid < NODES) {
            int n = n0 + tid;
            if (n < NN) {
                g_el[n] = s_pl[tid][0] + s_pl[tid][1] + s_pl[tid][2] + s_pl[tid][3];
                g_er[n] = s_pr[tid][0] + s_pr[tid][1] + s_pr[tid][2] + s_pr[tid][3];
            }
        }
    }
}

// ---------------------------------------------------------------------------
// Fused single-pass softmax + aggregation + bias + ELU (R14 + speculation).
// TWO nodes per warp (half-warp per node; lane owns 4 channels).
// SPECULATIVE load phase: all bucket LDGs issued unpredicated, in parallel
// with the cnt LDG (stale entries are valid src*64 offsets from the
// deterministic scatter; they are masked out of ssum/agg once cnt arrives).
// Chain shrinks from 3 serial L2 hops (cnt->bucket->el) to 2 (bucket->el).
// ---------------------------------------------------------------------------
template <int H>
__global__ void __launch_bounds__(256) gat_edge_kernel(const float* __restrict__ b,
                                                       float* __restrict__ out,
                                                       int do_elu) {
    __shared__ int s_off[8][2][CAP];                        // src*64
    __shared__ __align__(16) float s_ex[8][2][CAP * H];

    int wid  = threadIdx.x >> 5;
    int lane = threadIdx.x & 31;
    int half = lane >> 4;
    int li   = lane & 15;
    int n = blockIdx.x * 16 + wid * 2 + half;
    bool valid = (n < NN);
    int nc = valid ? n : (NN - 1);          // clamped index: loads always safe
    const int* bucket = &g_bucket[nc * CAP];

    // speculative bucket loads: unpredicated, issued before cnt is known
    int offr[4];
#pragma unroll
    for (int c = 0; c < 4; ++c) offr[c] = bucket[li + c * 16];

    int cnt = g_cnt[nc];                    // overlapped with bucket loads
    if (cnt > CAP) cnt = CAP;
    if (!valid) cnt = 0;

    float er_h[H];
    if (H == 4) {
        float4 e4 = *(const float4*)&g_er[nc * 4];
        er_h[0] = e4.x; er_h[1] = e4.y; er_h[2] = e4.z; er_h[3] = e4.w;
    } else {
        er_h[0] = g_er[nc];
    }

    float ssum[H];
#pragma unroll
    for (int h = 0; h < H; ++h) ssum[h] = 0.f;

    // el gathers + exp: speculative (depend only on bucket values); ssum
    // contribution predicated on idx<cnt.
#pragma unroll
    for (int c = 0; c < 4; ++c) {
        int idx = li + c * 16;
        int off = offr[c];
        s_off[wid][half][idx] = off;
        if (H == 4) {
            float4 e4 = *(const float4*)&g_el[off >> 4];   // g_el[src*4]
            float v0 = __expf(lrelu(e4.x + er_h[0]));
            float v1 = __expf(lrelu(e4.y + er_h[1]));
            float v2 = __expf(lrelu(e4.z + er_h[2]));
            float v3 = __expf(lrelu(e4.w + er_h[3]));
            *(float4*)&s_ex[wid][half][idx * 4] = make_float4(v0, v1, v2, v3);
            if (idx < cnt) {
                ssum[0] += v0; ssum[1] += v1; ssum[2] += v2; ssum[3] += v3;
            }
        } else {
            float v0 = __expf(lrelu(g_el[off >> 6] + er_h[0]));
            s_ex[wid][half][idx] = v0;
            if (idx < cnt) ssum[0] += v0;
        }
    }
    __syncwarp();

    // ---- aggregation: one unbroken loop over all edges of own node ----
    float4 acc = make_float4(0.f, 0.f, 0.f, 0.f);
    int hh = (H == 4) ? (li >> 2) : 0;     // head of channels li*4..li*4+3
#pragma unroll 4
    for (int j = 0; j < cnt; ++j) {
        int off = s_off[wid][half][j];
        float c = (H == 4) ? s_ex[wid][half][j * 4 + hh]
                           : s_ex[wid][half][j];
        float4 fv = *(const float4*)&g_f[off + li * 4];
        acc.x = fmaf(c, fv.x, acc.x);
        acc.y = fmaf(c, fv.y, acc.y);
        acc.z = fmaf(c, fv.z, acc.z);
        acc.w = fmaf(c, fv.w, acc.w);
    }

    // softmax denominators: reduce within the half-warp
#pragma unroll
    for (int o = 8; o > 0; o >>= 1)
#pragma unroll
        for (int h = 0; h < H; ++h)
            ssum[h] += __shfl_xor_sync(0xffffffffu, ssum[h], o);

    if (valid) {
        float4 bv = *(const float4*)&b[li * 4];
        float4 v;
        if (cnt > 0) {
            float inv = 1.f / ssum[hh];
            v.x = acc.x * inv + bv.x;
            v.y = acc.y * inv + bv.y;
            v.z = acc.z * inv + bv.z;
            v.w = acc.w * inv + bv.w;
        } else {
            v = bv;
        }
        if (do_elu) {
            v.x = v.x > 0.f ? v.x : expm1f(v.x);
            v.y = v.y > 0.f ? v.y : expm1f(v.y);
            v.z = v.z > 0.f ? v.z : expm1f(v.z);
            v.w = v.w > 0.f ? v.w : expm1f(v.w);
        }
        float* op = out ? out : g_x;
        *(float4*)&op[n * 64 + li * 4] = v;
    }
}

// ---------------------------------------------------------------------------
// Host driver — bucket build overlapped with layer-0 GEMM on a side stream.
// ---------------------------------------------------------------------------
extern "C" void kernel_launch(void* const* d_in, const int* in_sizes, int n_in,
                              void* d_out, int out_size) {
    const float* h   = (const float*)d_in[0];
    const int*   src = (const int*)  d_in[1];
    const int*   dst = (const int*)  d_in[2];
    const float* W0  = (const float*)d_in[3];
    const float* al0 = (const float*)d_in[4];
    const float* ar0 = (const float*)d_in[5];
    const float* b0  = (const float*)d_in[6];
    const float* W1  = (const float*)d_in[7];
    const float* al1 = (const float*)d_in[8];
    const float* ar1 = (const float*)d_in[9];
    const float* b1  = (const float*)d_in[10];
    const float* W2  = (const float*)d_in[11];
    const float* al2 = (const float*)d_in[12];
    const float* ar2 = (const float*)d_in[13];
    const float* b2  = (const float*)d_in[14];

    static cudaStream_t s2 = nullptr;
    static cudaEvent_t evFork = nullptr, evJoin = nullptr;
    if (!s2) {
        cudaStreamCreateWithFlags(&s2, cudaStreamNonBlocking);
        cudaEventCreateWithFlags(&evFork, cudaEventDisableTiming);
        cudaEventCreateWithFlags(&evJoin, cudaEventDisableTiming);
    }

    // Fork: bucket build on s2, layer-0 GEMM on main stream.
    cudaEventRecord(evFork, 0);
    cudaStreamWaitEvent(s2, evFork, 0);

    zero_cnt_kernel<<<(NN + 255) / 256, 256, 0, s2>>>();
    scatter_kernel <<<(EE + 255) / 256, 256, 0, s2>>>(src, dst);
    cudaEventRecord(evJoin, s2);

    int gblocks = (NN + 63) / 64;   // 782

    gemm_elr_kernel<128, 4><<<gblocks, 256>>>(h, W0, al0, ar0);

    cudaStreamWaitEvent(0, evJoin, 0);

    int eblocks = (NN + 15) / 16;   // 3125

    gat_edge_kernel<4><<<eblocks, 256>>>(b0, nullptr, 1);

    gemm_elr_kernel<64, 4><<<gblocks, 256>>>(nullptr, W1, al1, ar1);
    gat_edge_kernel<4><<<eblocks, 256>>>(b1, nullptr, 1);

    gemm_elr_kernel<64, 1><<<gblocks, 256>>>(nullptr, W2, al2, ar2);
    gat_edge_kernel<1><<<eblocks, 256>>>(b2, (float*)d_out, 0);
}